// round 2
// baseline (speedup 1.0000x reference)
#include <cuda_runtime.h>
#include <cuda_bf16.h>

// Problem constants
#define BB  2
#define SS  2048
#define DD  1024
#define HH  16
#define HDD 64
#define MM  (BB*SS)        // 4096 rows

// Scratch (device globals; allocation-free rule)
__device__ float g_q [BB*HH*SS*HDD];   // [b,h,s,hd]
__device__ float g_k [BB*HH*SS*HDD];
__device__ float g_v [BB*HH*SS*HDD];
__device__ float g_pm[BB*HH*SS*HDD];   // causal prefix-mean of v
__device__ float g_am[BB*SS*DD];       // attention output, merged heads [b*s, d]

// ---------------------------------------------------------------------------
// Kernel 1: fused projection GEMM.  Y = X @ [qk_w | v_w] (+ qk_b on first 2D)
// M=4096, K=1024, N=3072.  128x128x8 tile, 256 threads, 8x8 per thread.
// Epilogue scatters into head-major q/k/v.
// ---------------------------------------------------------------------------
__global__ __launch_bounds__(256, 2)
void proj_gemm(const float* __restrict__ X,  const float* __restrict__ QKW,
               const float* __restrict__ QKB, const float* __restrict__ VW)
{
    __shared__ float As[8*128];   // As[k][m]
    __shared__ float Bs[8*128];   // Bs[k][n]
    const int m0 = blockIdx.y * 128;
    const int n0 = blockIdx.x * 128;

    const float* Bp; int ldb, bn0;
    if (n0 < 2048) { Bp = QKW; ldb = 2048; bn0 = n0; }
    else           { Bp = VW;  ldb = 1024; bn0 = n0 - 2048; }

    const int tid  = threadIdx.x;
    const int arow = tid >> 1,  akq = (tid & 1) * 4;
    const int brow = tid >> 5,  bnq = (tid & 31) * 4;
    const int ty   = tid >> 4,  tx  = tid & 15;

    float acc[8][8];
    #pragma unroll
    for (int i = 0; i < 8; i++)
        #pragma unroll
        for (int j = 0; j < 8; j++) acc[i][j] = 0.f;

    float4 av = *(const float4*)&X [(m0 + arow) * 1024 + akq];
    float4 bv = *(const float4*)&Bp[brow * ldb + bn0 + bnq];

    for (int kt = 0; kt < 1024; kt += 8) {
        As[(akq+0)*128 + arow] = av.x;
        As[(akq+1)*128 + arow] = av.y;
        As[(akq+2)*128 + arow] = av.z;
        As[(akq+3)*128 + arow] = av.w;
        *(float4*)&Bs[brow * 128 + bnq] = bv;
        __syncthreads();
        if (kt + 8 < 1024) {
            av = *(const float4*)&X [(m0 + arow) * 1024 + kt + 8 + akq];
            bv = *(const float4*)&Bp[(kt + 8 + brow) * ldb + bn0 + bnq];
        }
        #pragma unroll
        for (int kk = 0; kk < 8; kk++) {
            float a[8], b[8];
            *(float4*)&a[0] = *(float4*)&As[kk*128 + ty*8];
            *(float4*)&a[4] = *(float4*)&As[kk*128 + ty*8 + 4];
            *(float4*)&b[0] = *(float4*)&Bs[kk*128 + tx*8];
            *(float4*)&b[4] = *(float4*)&Bs[kk*128 + tx*8 + 4];
            #pragma unroll
            for (int i = 0; i < 8; i++)
                #pragma unroll
                for (int j = 0; j < 8; j++)
                    acc[i][j] = fmaf(a[i], b[j], acc[i][j]);
        }
        __syncthreads();
    }

    // Epilogue: add bias, scatter to head-major layouts.
    float bias[8];
    #pragma unroll
    for (int j = 0; j < 8; j++) {
        int nn = n0 + tx*8 + j;
        bias[j] = (nn < 2048) ? QKB[nn] : 0.f;
    }
    #pragma unroll
    for (int i = 0; i < 8; i++) {
        int mm = m0 + ty*8 + i;
        int bb = mm >> 11, ss = mm & 2047;
        #pragma unroll
        for (int j = 0; j < 8; j++) {
            int nn = n0 + tx*8 + j;
            float val = acc[i][j] + bias[j];
            float* dst; int col;
            if (nn < 1024)      { dst = g_q; col = nn; }
            else if (nn < 2048) { dst = g_k; col = nn - 1024; }
            else                { dst = g_v; col = nn - 2048; }
            int h = col >> 6, hd = col & 63;
            dst[(((bb << 4) + h) * 2048 + ss) * 64 + hd] = val;
        }
    }
}

// ---------------------------------------------------------------------------
// Kernel 2: causal prefix mean of v:  pm[s] = (1/(s+1)) * sum_{k<=s} v[k]
// One block per (b,h), 1024 threads = 16 chunks x 64 hd.
// ---------------------------------------------------------------------------
__global__ __launch_bounds__(1024)
void prefix_kernel()
{
    const int bh = blockIdx.x;
    const float* vp = g_v  + bh * SS * HDD;
    float*       pp = g_pm + bh * SS * HDD;
    const int tid = threadIdx.x;
    const int hd  = tid & 63;
    const int c   = tid >> 6;           // 0..15, chunk of 128 rows
    __shared__ float cs[16][64];

    const int s0 = c * 128;
    float acc = 0.f;
    #pragma unroll 4
    for (int i = 0; i < 128; i++) acc += vp[(s0 + i) * 64 + hd];
    cs[c][hd] = acc;
    __syncthreads();

    float off = 0.f;
    for (int cc = 0; cc < c; cc++) off += cs[cc][hd];

    float run = off;
    #pragma unroll 4
    for (int i = 0; i < 128; i++) {
        int s = s0 + i;
        run += vp[s * 64 + hd];
        pp[s * 64 + hd] = run / (float)(s + 1);
    }
}

// ---------------------------------------------------------------------------
// Kernel 3: flash attention + shaped epilogue.
// Block = (q-tile of 64) x (b,h).  256 threads, 4x4 register tiles.
// smem: Qt[64][64] (hd-major), KP[64][64] (K hd-major, reused for P key-major),
//       Vs[64][64].  Total 48 KB dynamic (default limit, no attribute needed).
// ---------------------------------------------------------------------------
#define ATTN_SMEM (3 * 64 * 64 * 4)

__global__ __launch_bounds__(256, 2)
void attn_kernel(const float* __restrict__ RG, const float* __restrict__ SG,
                 const float* __restrict__ CG)
{
    extern __shared__ float smf[];
    float* Qt = smf;                // Qt[hd][q]
    float* KP = smf + 64*64;        // Kt[hd][key]  then  Pt[key][q]
    float* Vs = smf + 2*64*64;      // Vs[key][hd]

    const int qt = blockIdx.x, bh = blockIdx.y;
    const int h  = bh & 15;
    const float* qp = g_q  + bh * SS * HDD;
    const float* kp = g_k  + bh * SS * HDD;
    const float* vp = g_v  + bh * SS * HDD;
    const float* pp = g_pm + bh * SS * HDD;

    const int tid = threadIdx.x;
    const int lr  = tid >> 4;           // 0..15 (load row group)
    const int lc  = (tid & 15) * 4;     // 0..60 (load col quad)
    const int ty  = tid >> 4, tx = tid & 15;
    const int ty4 = ty * 4, tx4 = tx * 4;
    const int q0  = qt * 64;

    // Load Q tile transposed (hd-major)
    #pragma unroll
    for (int rr = 0; rr < 4; rr++) {
        int row = rr * 16 + lr;
        float4 t = *(const float4*)&qp[(q0 + row) * 64 + lc];
        Qt[(lc+0)*64 + row] = t.x;
        Qt[(lc+1)*64 + row] = t.y;
        Qt[(lc+2)*64 + row] = t.z;
        Qt[(lc+3)*64 + row] = t.w;
    }

    float o[4][4] = {};
    float mrow[4], lrow[4];
    #pragma unroll
    for (int i = 0; i < 4; i++) { mrow[i] = -1e30f; lrow[i] = 0.f; }
    __syncthreads();

    const int nkv = qt + 1;
    for (int kv = 0; kv < nkv; kv++) {
        const int k0 = kv * 64;
        // Load K transposed + V natural
        #pragma unroll
        for (int rr = 0; rr < 4; rr++) {
            int row = rr * 16 + lr;
            float4 t = *(const float4*)&kp[(k0 + row) * 64 + lc];
            KP[(lc+0)*64 + row] = t.x;
            KP[(lc+1)*64 + row] = t.y;
            KP[(lc+2)*64 + row] = t.z;
            KP[(lc+3)*64 + row] = t.w;
            *(float4*)&Vs[row * 64 + lc] = *(const float4*)&vp[(k0 + row) * 64 + lc];
        }
        __syncthreads();

        // Scores: S = Q K^T  (reduce over hd)
        float sv[4][4] = {};
        #pragma unroll 8
        for (int kk = 0; kk < 64; kk++) {
            float4 a = *(float4*)&Qt[kk*64 + ty4];
            float4 b = *(float4*)&KP[kk*64 + tx4];
            float aa[4] = {a.x, a.y, a.z, a.w};
            float bb[4] = {b.x, b.y, b.z, b.w};
            #pragma unroll
            for (int i = 0; i < 4; i++)
                #pragma unroll
                for (int j = 0; j < 4; j++)
                    sv[i][j] = fmaf(aa[i], bb[j], sv[i][j]);
        }

        // Online softmax (row state shared by the 16 lanes of each ty-group)
        const bool diag = (kv == nkv - 1);
        float p[4][4];
        #pragma unroll
        for (int i = 0; i < 4; i++) {
            const int qq = q0 + ty4 + i;
            float mt = -1e30f;
            #pragma unroll
            for (int j = 0; j < 4; j++) {
                float s = sv[i][j] * 0.125f;            // 1/sqrt(64)
                if (diag && (k0 + tx4 + j > qq)) s = -1e30f;
                sv[i][j] = s;
                mt = fmaxf(mt, s);
            }
            mt = fmaxf(mt, __shfl_xor_sync(0xffffffffu, mt, 1, 16));
            mt = fmaxf(mt, __shfl_xor_sync(0xffffffffu, mt, 2, 16));
            mt = fmaxf(mt, __shfl_xor_sync(0xffffffffu, mt, 4, 16));
            mt = fmaxf(mt, __shfl_xor_sync(0xffffffffu, mt, 8, 16));
            float mnew = fmaxf(mrow[i], mt);
            float corr = __expf(mrow[i] - mnew);
            mrow[i] = mnew;
            float ssum = 0.f;
            #pragma unroll
            for (int j = 0; j < 4; j++) {
                float pv = __expf(sv[i][j] - mnew);
                p[i][j] = pv;
                ssum += pv;
            }
            ssum += __shfl_xor_sync(0xffffffffu, ssum, 1, 16);
            ssum += __shfl_xor_sync(0xffffffffu, ssum, 2, 16);
            ssum += __shfl_xor_sync(0xffffffffu, ssum, 4, 16);
            ssum += __shfl_xor_sync(0xffffffffu, ssum, 8, 16);
            lrow[i] = lrow[i] * corr + ssum;
            #pragma unroll
            for (int j = 0; j < 4; j++) o[i][j] *= corr;
        }

        __syncthreads();   // everyone done reading K before P overwrites KP
        // Store P transposed (key-major) into KP
        #pragma unroll
        for (int j = 0; j < 4; j++)
            *(float4*)&KP[(tx4 + j) * 64 + ty4] =
                make_float4(p[0][j], p[1][j], p[2][j], p[3][j]);
        __syncthreads();

        // O += P @ V  (reduce over key)
        #pragma unroll 8
        for (int kk = 0; kk < 64; kk++) {
            float4 a = *(float4*)&KP[kk*64 + ty4];
            float4 b = *(float4*)&Vs[kk*64 + tx4];
            float aa[4] = {a.x, a.y, a.z, a.w};
            float bb[4] = {b.x, b.y, b.z, b.w};
            #pragma unroll
            for (int i = 0; i < 4; i++)
                #pragma unroll
                for (int j = 0; j < 4; j++)
                    o[i][j] = fmaf(aa[i], bb[j], o[i][j]);
        }
        __syncthreads();   // before next tile overwrites KP / Vs
    }

    // Shaped epilogue: rg*softmaxV + sg*v - cg*prefix_mean, merged-head store
    const float rgv = RG[h], sgv = SG[h], cgv = CG[h];
    const int bI = bh >> 4;
    #pragma unroll
    for (int i = 0; i < 4; i++) {
        const int qq = q0 + ty4 + i;
        const float inv = 1.f / lrow[i];
        float4 vv  = *(const float4*)&vp[qq * 64 + tx4];
        float4 pm4 = *(const float4*)&pp[qq * 64 + tx4];
        float4 r;
        r.x = rgv * o[i][0] * inv + sgv * vv.x - cgv * pm4.x;
        r.y = rgv * o[i][1] * inv + sgv * vv.y - cgv * pm4.y;
        r.z = rgv * o[i][2] * inv + sgv * vv.z - cgv * pm4.z;
        r.w = rgv * o[i][3] * inv + sgv * vv.w - cgv * pm4.w;
        *(float4*)&g_am[(bI * SS + qq) * DD + h * 64 + tx4] = r;
    }
}

// ---------------------------------------------------------------------------
// Kernel 4: c_proj GEMM.  OUT = g_am @ W.  M=4096, K=1024, N=1024.
// ---------------------------------------------------------------------------
__global__ __launch_bounds__(256, 2)
void out_gemm(const float* __restrict__ W, float* __restrict__ OUT)
{
    __shared__ float As[8*128];
    __shared__ float Bs[8*128];
    const int m0 = blockIdx.y * 128;
    const int n0 = blockIdx.x * 128;
    const int tid  = threadIdx.x;
    const int arow = tid >> 1,  akq = (tid & 1) * 4;
    const int brow = tid >> 5,  bnq = (tid & 31) * 4;
    const int ty   = tid >> 4,  tx  = tid & 15;

    float acc[8][8];
    #pragma unroll
    for (int i = 0; i < 8; i++)
        #pragma unroll
        for (int j = 0; j < 8; j++) acc[i][j] = 0.f;

    float4 av = *(const float4*)&g_am[(m0 + arow) * 1024 + akq];
    float4 bv = *(const float4*)&W   [brow * 1024 + n0 + bnq];

    for (int kt = 0; kt < 1024; kt += 8) {
        As[(akq+0)*128 + arow] = av.x;
        As[(akq+1)*128 + arow] = av.y;
        As[(akq+2)*128 + arow] = av.z;
        As[(akq+3)*128 + arow] = av.w;
        *(float4*)&Bs[brow * 128 + bnq] = bv;
        __syncthreads();
        if (kt + 8 < 1024) {
            av = *(const float4*)&g_am[(m0 + arow) * 1024 + kt + 8 + akq];
            bv = *(const float4*)&W   [(kt + 8 + brow) * 1024 + n0 + bnq];
        }
        #pragma unroll
        for (int kk = 0; kk < 8; kk++) {
            float a[8], b[8];
            *(float4*)&a[0] = *(float4*)&As[kk*128 + ty*8];
            *(float4*)&a[4] = *(float4*)&As[kk*128 + ty*8 + 4];
            *(float4*)&b[0] = *(float4*)&Bs[kk*128 + tx*8];
            *(float4*)&b[4] = *(float4*)&Bs[kk*128 + tx*8 + 4];
            #pragma unroll
            for (int i = 0; i < 8; i++)
                #pragma unroll
                for (int j = 0; j < 8; j++)
                    acc[i][j] = fmaf(a[i], b[j], acc[i][j]);
        }
        __syncthreads();
    }

    #pragma unroll
    for (int i = 0; i < 8; i++) {
        int mm = m0 + ty*8 + i;
        float* op = &OUT[mm * 1024 + n0 + tx*8];
        *(float4*)&op[0] = make_float4(acc[i][0], acc[i][1], acc[i][2], acc[i][3]);
        *(float4*)&op[4] = make_float4(acc[i][4], acc[i][5], acc[i][6], acc[i][7]);
    }
}

// ---------------------------------------------------------------------------
extern "C" void kernel_launch(void* const* d_in, const int* in_sizes, int n_in,
                              void* d_out, int out_size)
{
    (void)in_sizes; (void)n_in; (void)out_size;
    const float* x      = (const float*)d_in[0];
    const float* qk_w   = (const float*)d_in[1];
    const float* qk_b   = (const float*)d_in[2];
    const float* v_w    = (const float*)d_in[3];
    const float* cprojw = (const float*)d_in[4];
    const float* rg     = (const float*)d_in[5];
    const float* sg     = (const float*)d_in[6];
    const float* cg     = (const float*)d_in[7];

    proj_gemm<<<dim3(24, 32), 256>>>(x, qk_w, qk_b, v_w);
    prefix_kernel<<<BB * HH, 1024>>>();
    attn_kernel<<<dim3(SS / 64, BB * HH), 256, ATTN_SMEM>>>(rg, sg, cg);
    out_gemm<<<dim3(8, 32), 256>>>(cprojw, (float*)d_out);
}